// round 14
// baseline (speedup 1.0000x reference)
#include <cuda_runtime.h>
#include <cuda_bf16.h>
#include <math.h>
#include <stdint.h>

#define MAXN 50000
#define MAXE 800000
#define FD   256
typedef unsigned long long u64;
typedef __nv_bfloat16 bf16;
typedef __nv_bfloat162 bf162;

// ---------------- scratch (static device globals; no allocation) -------------
__device__ __align__(16) float g_h0[(size_t)MAXN * FD];
__device__ __align__(16) float g_h1[(size_t)MAXN * FD];
__device__ __align__(16) bf16 g_aggh[(size_t)MAXN * FD];
__device__ __align__(16) bf16 g_aggl[(size_t)MAXN * FD];
__device__ __align__(16) bf16 g_rt0h[(size_t)MAXN * FD];
__device__ __align__(16) bf16 g_rt0l[(size_t)MAXN * FD];
__device__ __align__(16) bf16 g_rt1h[(size_t)MAXN * FD];
__device__ __align__(16) bf16 g_rt1l[(size_t)MAXN * FD];
__device__ __align__(16) bf16 g_Bth[3][512 * 256];   // W^T stacked [n=256][k=512], hi
__device__ __align__(16) bf16 g_Btl[3][512 * 256];   // lo
__device__ int g_deg   [MAXN];
__device__ int g_cursor[MAXN];
__device__ int g_rowptr[MAXN + 1];
__device__ int g_col   [MAXE];
__device__ int g_tmp   [MAXN];
__device__ int g_bsum  [128];
__device__ int g_is64;

// ---------------- PTX helpers (baseline ISA only — no 'a' features) ----------
__device__ __forceinline__ uint32_t s2u(const void* p) {
    uint32_t a;
    asm("{ .reg .u64 t; cvta.to.shared.u64 t, %1; cvt.u32.u64 %0, t; }"
        : "=r"(a) : "l"(p));
    return a;
}
__device__ __forceinline__ void ldm4(uint32_t* r, uint32_t addr) {
    asm volatile("ldmatrix.sync.aligned.m8n8.x4.shared.b16 {%0,%1,%2,%3}, [%4];"
                 : "=r"(r[0]), "=r"(r[1]), "=r"(r[2]), "=r"(r[3]) : "r"(addr));
}
__device__ __forceinline__ void mma16816(float* d, const uint32_t* a, const uint32_t* b) {
    asm volatile(
        "mma.sync.aligned.m16n8k16.row.col.f32.bf16.bf16.f32 "
        "{%0,%1,%2,%3}, {%4,%5,%6,%7}, {%8,%9}, {%0,%1,%2,%3};"
        : "+f"(d[0]), "+f"(d[1]), "+f"(d[2]), "+f"(d[3])
        : "r"(a[0]), "r"(a[1]), "r"(a[2]), "r"(a[3]), "r"(b[0]), "r"(b[1]));
}
__device__ __forceinline__ void cpa16(uint32_t dst, const void* src) {
    asm volatile("cp.async.ca.shared.global [%0], [%1], 16;"
                 :: "r"(dst), "l"(src) : "memory");
}
#define CP_COMMIT() asm volatile("cp.async.commit_group;" ::: "memory")
#define CP_WAIT1()  asm volatile("cp.async.wait_group 1;" ::: "memory")
#define CP_WAIT0()  asm volatile("cp.async.wait_group 0;" ::: "memory")

__device__ __forceinline__ void split2(float v, bf16& h, bf16& l) {
    h = __float2bfloat16_rn(v);
    l = __float2bfloat16_rn(v - __bfloat162float(h));
}

// ---------------- edge-index dtype probe -------------------------------------
__global__ void k_detect(const int* __restrict__ ei_w) {
    int all_zero = 1;
    for (int i = 0; i < 128; i++)
        if (ei_w[2 * i + 1] != 0) { all_zero = 0; break; }
    g_is64 = all_zero;
}
__device__ __forceinline__ int load_idx(const void* ei, size_t pos, int nmax) {
    int v;
    if (g_is64) v = (int)((const long long*)ei)[pos];
    else        v = ((const int*)ei)[pos];
    return min(max(v, 0), nmax - 1);
}

// ---------------- CSR build --------------------------------------------------
__global__ void k_zero(int n) {
    int i = blockIdx.x * blockDim.x + threadIdx.x;
    if (i < n) { g_deg[i] = 0; g_cursor[i] = 0; }
}
__global__ void k_hist(const void* __restrict__ ei, int E, int Nn) {
    int e = blockIdx.x * blockDim.x + threadIdx.x;
    if (e < E) atomicAdd(&g_deg[load_idx(ei, (size_t)E + e, Nn)], 1);
}
#define SCAN_T 512
__global__ void k_scanA(int n) {
    __shared__ int sh[SCAN_T];
    int b = blockIdx.x, t = threadIdx.x;
    int i = b * SCAN_T + t;
    int v = (i < n) ? g_deg[i] : 0;
    sh[t] = v;
    __syncthreads();
    for (int off = 1; off < SCAN_T; off <<= 1) {
        int u = (t >= off) ? sh[t - off] : 0;
        __syncthreads();
        sh[t] += u;
        __syncthreads();
    }
    if (i < n) g_tmp[i] = sh[t];
    if (t == SCAN_T - 1) g_bsum[b] = sh[t];
}
__global__ void k_scanB(int nb) {
    __shared__ int sh[128];
    int t = threadIdx.x;
    sh[t] = (t < nb) ? g_bsum[t] : 0;
    __syncthreads();
    for (int off = 1; off < 128; off <<= 1) {
        int u = (t >= off) ? sh[t - off] : 0;
        __syncthreads();
        sh[t] += u;
        __syncthreads();
    }
    if (t < nb) g_bsum[t] = sh[t];
}
__global__ void k_scanC(int n) {
    int b = blockIdx.x, t = threadIdx.x;
    int i = b * SCAN_T + t;
    if (i < n) {
        int boff = (b == 0) ? 0 : g_bsum[b - 1];
        g_rowptr[i] = boff + g_tmp[i] - g_deg[i];
        if (i == n - 1) g_rowptr[n] = boff + g_tmp[i];
    }
}
__global__ void k_fill(const void* __restrict__ ei, int E, int Nn) {
    int e = blockIdx.x * blockDim.x + threadIdx.x;
    if (e < E) {
        int s = load_idx(ei, (size_t)e, Nn);
        int d = load_idx(ei, (size_t)E + e, Nn);
        int pos = atomicAdd(&g_cursor[d], 1);
        g_col[g_rowptr[d] + pos] = s;
    }
}

// ---------------- conversions ------------------------------------------------
__global__ void k_cvt(const float* __restrict__ x, bf16* __restrict__ oh,
                      bf16* __restrict__ ol, int n4) {
    int i = blockIdx.x * blockDim.x + threadIdx.x;
    if (i < n4) {
        float4 v = ((const float4*)x)[i];
        bf16 h0, l0, h1, l1, h2, l2, h3, l3;
        split2(v.x, h0, l0); split2(v.y, h1, l1);
        split2(v.z, h2, l2); split2(v.w, h3, l3);
        ((bf162*)oh)[2 * i]     = bf162{h0, h1};
        ((bf162*)oh)[2 * i + 1] = bf162{h2, h3};
        ((bf162*)ol)[2 * i]     = bf162{l0, l1};
        ((bf162*)ol)[2 * i + 1] = bf162{l2, l3};
    }
}
// weights -> transposed stacked bf16 hi/lo: Bt[n*512 + k]; k<256: Wrel, else Wroot
__global__ void k_cvtw(const float* __restrict__ Wrel, const float* __restrict__ Wroot,
                       bf16* __restrict__ oh, bf16* __restrict__ ol) {
    int idx = blockIdx.x * blockDim.x + threadIdx.x;   // 0..131071
    int n = idx >> 9, k = idx & 511;
    float w = (k < 256) ? Wrel[k * FD + n] : Wroot[(k - 256) * FD + n];
    bf16 h, l;
    split2(w, h, l);
    oh[idx] = h; ol[idx] = l;
}

// ---------------- aggregation (fp32 gather -> bf16 hi/lo out) -----------------
__global__ void k_agg(const float* __restrict__ x, bf16* __restrict__ oh,
                      bf16* __restrict__ ol) {
    int node = blockIdx.x;
    int c = threadIdx.x * 4;
    float4 a0 = make_float4(0.f, 0.f, 0.f, 0.f);
    float4 a1 = make_float4(0.f, 0.f, 0.f, 0.f);
    int beg = g_rowptr[node];
    int end = g_rowptr[node + 1];
    int j = beg;
    for (; j + 1 < end; j += 2) {
        int s0 = g_col[j], s1 = g_col[j + 1];
        float4 v0 = *(const float4*)(x + (size_t)s0 * FD + c);
        float4 v1 = *(const float4*)(x + (size_t)s1 * FD + c);
        a0.x += v0.x; a0.y += v0.y; a0.z += v0.z; a0.w += v0.w;
        a1.x += v1.x; a1.y += v1.y; a1.z += v1.z; a1.w += v1.w;
    }
    if (j < end) {
        int s0 = g_col[j];
        float4 v0 = *(const float4*)(x + (size_t)s0 * FD + c);
        a0.x += v0.x; a0.y += v0.y; a0.z += v0.z; a0.w += v0.w;
    }
    a0.x += a1.x; a0.y += a1.y; a0.z += a1.z; a0.w += a1.w;
    bf16 h0, l0, h1, l1, h2, l2, h3, l3;
    split2(a0.x, h0, l0); split2(a0.y, h1, l1);
    split2(a0.z, h2, l2); split2(a0.w, h3, l3);
    size_t o = (size_t)node * FD + c;
    *(bf162*)(oh + o)     = bf162{h0, h1};
    *(bf162*)(oh + o + 2) = bf162{h2, h3};
    *(bf162*)(ol + o)     = bf162{l0, l1};
    *(bf162*)(ol + o + 2) = bf162{l2, l3};
}

// ---------------- HMMA dual-GEMM + bias + ELU (bf16x3, cp.async 2-stage) ------
// CTA: 128 rows x 128 cols (grid.y = col half). K = 512 flattened
// (agg k<256, root k>=256), BK=32/iter, 16 iters. 8 warps 2x4, warp = 64x32.
#define LDT   40                            // padded row stride (80 B, 16B-aligned)
#define TILE_B (128 * LDT * 2)              // 10240 B per tile
#define STAGE_B (4 * TILE_B)                // Ah, Al, Bh, Bl
#define SMEM_DYN (2 * STAGE_B)              // 81920 B

__global__ __launch_bounds__(256)
void k_hmma(const bf16* __restrict__ aggh, const bf16* __restrict__ aggl,
            const bf16* __restrict__ rth,  const bf16* __restrict__ rtl,
            const bf16* __restrict__ Bth,  const bf16* __restrict__ Btl,
            const float* __restrict__ bias,
            float* __restrict__ out32,
            bf16* __restrict__ orth, bf16* __restrict__ ortl, int M) {
    extern __shared__ char dsm[];
    uint32_t sbase = s2u(dsm);

    int t = threadIdx.x, lane = t & 31, wid = t >> 5;
    int wm = wid >> 2, wn = wid & 3;          // 2 x 4 warp grid
    int brow = blockIdx.x * 128;
    int bcol = blockIdx.y * 128;

    float acc[4][4][4];
#pragma unroll
    for (int i = 0; i < 4; i++)
#pragma unroll
        for (int j = 0; j < 4; j++)
#pragma unroll
            for (int r = 0; r < 4; r++) acc[i][j][r] = 0.f;

    // per-thread tile-load coordinates (2 uint4 per tile per thread)
    int r0 = t >> 2, c0 = t & 3;
    int r1 = (t + 256) >> 2, c1 = (t + 256) & 3;
    int ga0 = min(brow + r0, M - 1), ga1 = min(brow + r1, M - 1);
    int gb0 = bcol + r0, gb1 = bcol + r1;
    uint32_t sm0 = (uint32_t)((r0 * LDT + c0 * 8) * 2);
    uint32_t sm1 = (uint32_t)((r1 * LDT + c1 * 8) * 2);

    auto prefetch = [&](int it) {
        int kb = it * 32;
        const bf16 *Ah, *Al;
        int acol;
        if (kb < 256) { Ah = aggh; Al = aggl; acol = kb; }
        else          { Ah = rth;  Al = rtl;  acol = kb - 256; }
        uint32_t sb = sbase + (uint32_t)(it & 1) * STAGE_B;
        cpa16(sb + sm0,              Ah + (size_t)ga0 * FD + acol + c0 * 8);
        cpa16(sb + sm1,              Ah + (size_t)ga1 * FD + acol + c1 * 8);
        cpa16(sb + TILE_B + sm0,     Al + (size_t)ga0 * FD + acol + c0 * 8);
        cpa16(sb + TILE_B + sm1,     Al + (size_t)ga1 * FD + acol + c1 * 8);
        cpa16(sb + 2 * TILE_B + sm0, Bth + (size_t)gb0 * 512 + kb + c0 * 8);
        cpa16(sb + 2 * TILE_B + sm1, Bth + (size_t)gb1 * 512 + kb + c1 * 8);
        cpa16(sb + 3 * TILE_B + sm0, Btl + (size_t)gb0 * 512 + kb + c0 * 8);
        cpa16(sb + 3 * TILE_B + sm1, Btl + (size_t)gb1 * 512 + kb + c1 * 8);
        CP_COMMIT();
    };

    prefetch(0);

    for (int it = 0; it < 16; it++) {
        if (it + 1 < 16) { prefetch(it + 1); CP_WAIT1(); }
        else             { CP_WAIT0(); }
        __syncthreads();

        uint32_t sb  = sbase + (uint32_t)(it & 1) * STAGE_B;
        uint32_t uAh = sb, uAl = sb + TILE_B;
        uint32_t uBh = sb + 2 * TILE_B, uBl = sb + 3 * TILE_B;

#pragma unroll
        for (int ks = 0; ks < 2; ks++) {
            uint32_t aoff = (uint32_t)(((wm * 64 + (lane & 15)) * LDT
                                        + ks * 16 + (lane >> 4) * 8) * 2);
            uint32_t boff = (uint32_t)(((wn * 32 + (lane & 15)) * LDT
                                        + ks * 16 + (lane >> 4) * 8) * 2);
            uint32_t ah[4][4], al[4][4];
#pragma unroll
            for (int mf = 0; mf < 4; mf++) {
                ldm4(ah[mf], uAh + aoff + mf * 16 * LDT * 2);
                ldm4(al[mf], uAl + aoff + mf * 16 * LDT * 2);
            }
            uint32_t bh[4][2], bl[4][2];
#pragma unroll
            for (int np = 0; np < 2; np++) {
                uint32_t rh[4], rl[4];
                ldm4(rh, uBh + boff + np * 16 * LDT * 2);
                ldm4(rl, uBl + boff + np * 16 * LDT * 2);
                bh[2 * np][0] = rh[0]; bh[2 * np + 1][0] = rh[1];
                bh[2 * np][1] = rh[2]; bh[2 * np + 1][1] = rh[3];
                bl[2 * np][0] = rl[0]; bl[2 * np + 1][0] = rl[1];
                bl[2 * np][1] = rl[2]; bl[2 * np + 1][1] = rl[3];
            }
#pragma unroll
            for (int mf = 0; mf < 4; mf++)
#pragma unroll
                for (int nf = 0; nf < 4; nf++) {
                    mma16816(acc[mf][nf], ah[mf], bh[nf]);   // Ah*Bh
                    mma16816(acc[mf][nf], ah[mf], bl[nf]);   // Ah*Bl
                    mma16816(acc[mf][nf], al[mf], bh[nf]);   // Al*Bh
                }
        }
        __syncthreads();   // stage (it&1) free for reuse at it+2's prefetch
    }

    // epilogue: bias + ELU + fp32 store (+ bf16 hi/lo for next layer)
#pragma unroll
    for (int mf = 0; mf < 4; mf++) {
#pragma unroll
        for (int half = 0; half < 2; half++) {
            int grow = brow + wm * 64 + mf * 16 + (lane >> 2) + half * 8;
            if (grow < M) {
#pragma unroll
                for (int nf = 0; nf < 4; nf++) {
                    int gcol = bcol + wn * 32 + nf * 8 + (lane & 3) * 2;
                    float v0 = acc[mf][nf][half * 2]     + bias[gcol];
                    float v1 = acc[mf][nf][half * 2 + 1] + bias[gcol + 1];
                    v0 = (v0 > 0.f) ? v0 : expm1f(v0);
                    v1 = (v1 > 0.f) ? v1 : expm1f(v1);
                    size_t go = (size_t)grow * FD + gcol;
                    *(float2*)(out32 + go) = make_float2(v0, v1);
                    if (orth) {
                        bf16 h0, l0, h1, l1;
                        split2(v0, h0, l0); split2(v1, h1, l1);
                        *(bf162*)(orth + go) = bf162{h0, h1};
                        *(bf162*)(ortl + go) = bf162{l0, l1};
                    }
                }
            }
        }
    }
}

// ---------------- launch -----------------------------------------------------
extern "C" void kernel_launch(void* const* d_in, const int* in_sizes, int n_in,
                              void* d_out, int out_size) {
    const float* x   = (const float*)d_in[0];
    const void*  ei  = d_in[1];
    const float* W1r = (const float*)d_in[2];
    const float* b1  = (const float*)d_in[3];
    const float* W1o = (const float*)d_in[4];
    const float* W2r = (const float*)d_in[5];
    const float* b2  = (const float*)d_in[6];
    const float* W2o = (const float*)d_in[7];
    const float* W3r = (const float*)d_in[8];
    const float* b3  = (const float*)d_in[9];
    const float* W3o = (const float*)d_in[10];
    float* out = (float*)d_out;

    int Nn = in_sizes[0] / FD;      // 50000
    int E  = in_sizes[1] / 2;       // 800000

    float *h0, *h1;
    bf16 *aggh, *aggl, *rt0h, *rt0l, *rt1h, *rt1l, *Bth, *Btl;
    cudaGetSymbolAddress((void**)&h0,   g_h0);
    cudaGetSymbolAddress((void**)&h1,   g_h1);
    cudaGetSymbolAddress((void**)&aggh, g_aggh);
    cudaGetSymbolAddress((void**)&aggl, g_aggl);
    cudaGetSymbolAddress((void**)&rt0h, g_rt0h);
    cudaGetSymbolAddress((void**)&rt0l, g_rt0l);
    cudaGetSymbolAddress((void**)&rt1h, g_rt1h);
    cudaGetSymbolAddress((void**)&rt1l, g_rt1l);
    cudaGetSymbolAddress((void**)&Bth,  g_Bth);
    cudaGetSymbolAddress((void**)&Btl,  g_Btl);

    cudaFuncSetAttribute(k_hmma, cudaFuncAttributeMaxDynamicSharedMemorySize, SMEM_DYN);

    // CSR build
    k_detect<<<1, 1>>>((const int*)ei);
    k_zero<<<(Nn + 255) / 256, 256>>>(Nn);
    k_hist<<<(E + 255) / 256, 256>>>(ei, E, Nn);
    int nsb = (Nn + SCAN_T - 1) / SCAN_T;
    k_scanA<<<nsb, SCAN_T>>>(Nn);
    k_scanB<<<1, 128>>>(nsb);
    k_scanC<<<nsb, SCAN_T>>>(Nn);
    k_fill<<<(E + 255) / 256, 256>>>(ei, E, Nn);

    // weight + input conversions
    k_cvtw<<<512, 256>>>(W1r, W1o, Bth,                 Btl);
    k_cvtw<<<512, 256>>>(W2r, W2o, Bth + 512 * 256,     Btl + 512 * 256);
    k_cvtw<<<512, 256>>>(W3r, W3o, Bth + 2 * 512 * 256, Btl + 2 * 512 * 256);
    int n4 = Nn * FD / 4;
    k_cvt<<<(n4 + 255) / 256, 256>>>(x, rt0h, rt0l, n4);

    dim3 gg((Nn + 127) / 128, 2);

    // layer 1
    k_agg<<<Nn, 64>>>(x, aggh, aggl);
    k_hmma<<<gg, 256, SMEM_DYN>>>(aggh, aggl, rt0h, rt0l, Bth, Btl,
                                  b1, h0, rt1h, rt1l, Nn);
    // layer 2
    k_agg<<<Nn, 64>>>(h0, aggh, aggl);
    k_hmma<<<gg, 256, SMEM_DYN>>>(aggh, aggl, rt1h, rt1l,
                                  Bth + 512 * 256, Btl + 512 * 256,
                                  b2, h1, rt0h, rt0l, Nn);
    // layer 3 -> final fp32 output only
    k_agg<<<Nn, 64>>>(h1, aggh, aggl);
    k_hmma<<<gg, 256, SMEM_DYN>>>(aggh, aggl, rt0h, rt0l,
                                  Bth + 2 * 512 * 256, Btl + 2 * 512 * 256,
                                  b3, out, (bf16*)nullptr, (bf16*)nullptr, Nn);
}

// round 15
// speedup vs baseline: 1.1254x; 1.1254x over previous
#include <cuda_runtime.h>
#include <cuda_bf16.h>
#include <math.h>
#include <stdint.h>

#define MAXN 50000
#define MAXE 800000
#define FD   256
typedef unsigned long long u64;
typedef __nv_bfloat16 bf16;
typedef __nv_bfloat162 bf162;

// ---------------- scratch (static device globals; no allocation) -------------
__device__ __align__(16) bf16 g_aggh[(size_t)MAXN * FD];
__device__ __align__(16) bf16 g_aggl[(size_t)MAXN * FD];
__device__ __align__(16) bf16 g_rt0h[(size_t)MAXN * FD];
__device__ __align__(16) bf16 g_rt0l[(size_t)MAXN * FD];
__device__ __align__(16) bf16 g_rt1h[(size_t)MAXN * FD];
__device__ __align__(16) bf16 g_rt1l[(size_t)MAXN * FD];
__device__ __align__(16) bf16 g_Bth[3][512 * 256];   // W^T stacked [n=256][k=512], hi
__device__ __align__(16) bf16 g_Btl[3][512 * 256];   // lo
__device__ int g_deg   [MAXN];
__device__ int g_cursor[MAXN];
__device__ int g_rowptr[MAXN + 1];
__device__ int g_col   [MAXE];
__device__ int g_tmp   [MAXN];
__device__ int g_bsum  [128];
__device__ int g_is64;

// ---------------- PTX helpers (baseline ISA only — no 'a' features) ----------
__device__ __forceinline__ uint32_t s2u(const void* p) {
    uint32_t a;
    asm("{ .reg .u64 t; cvta.to.shared.u64 t, %1; cvt.u32.u64 %0, t; }"
        : "=r"(a) : "l"(p));
    return a;
}
__device__ __forceinline__ void ldm4(uint32_t* r, uint32_t addr) {
    asm volatile("ldmatrix.sync.aligned.m8n8.x4.shared.b16 {%0,%1,%2,%3}, [%4];"
                 : "=r"(r[0]), "=r"(r[1]), "=r"(r[2]), "=r"(r[3]) : "r"(addr));
}
__device__ __forceinline__ void mma16816(float* d, const uint32_t* a, const uint32_t* b) {
    asm volatile(
        "mma.sync.aligned.m16n8k16.row.col.f32.bf16.bf16.f32 "
        "{%0,%1,%2,%3}, {%4,%5,%6,%7}, {%8,%9}, {%0,%1,%2,%3};"
        : "+f"(d[0]), "+f"(d[1]), "+f"(d[2]), "+f"(d[3])
        : "r"(a[0]), "r"(a[1]), "r"(a[2]), "r"(a[3]), "r"(b[0]), "r"(b[1]));
}
__device__ __forceinline__ void cpa16(uint32_t dst, const void* src) {
    asm volatile("cp.async.ca.shared.global [%0], [%1], 16;"
                 :: "r"(dst), "l"(src) : "memory");
}
#define CP_COMMIT() asm volatile("cp.async.commit_group;" ::: "memory")
#define CP_WAIT0()  asm volatile("cp.async.wait_group 0;" ::: "memory")

__device__ __forceinline__ void split2(float v, bf16& h, bf16& l) {
    h = __float2bfloat16_rn(v);
    l = __float2bfloat16_rn(v - __bfloat162float(h));
}
// packed: float2 -> (hi bf162, lo bf162)
__device__ __forceinline__ void split2p(float2 v, bf162& hp, bf162& lp) {
    hp = __float22bfloat162_rn(v);
    float2 hf = __bfloat1622float2(hp);
    lp = __float22bfloat162_rn(make_float2(v.x - hf.x, v.y - hf.y));
}
// fast ELU: poly for small |v|, __expf otherwise; elementwise err ~3e-5
__device__ __forceinline__ float elu1(float v) {
    float p = v * fmaf(v, fmaf(v, fmaf(v, 0.041666667f, 0.16666667f), 0.5f), 1.f);
    float e = __expf(v) - 1.f;
    float neg = (v > -0.25f) ? p : e;
    return (v > 0.f) ? v : neg;
}

// ---------------- edge-index dtype probe -------------------------------------
__global__ void k_detect(const int* __restrict__ ei_w) {
    int all_zero = 1;
    for (int i = 0; i < 128; i++)
        if (ei_w[2 * i + 1] != 0) { all_zero = 0; break; }
    g_is64 = all_zero;
}
__device__ __forceinline__ int load_idx(const void* ei, size_t pos, int nmax) {
    int v;
    if (g_is64) v = (int)((const long long*)ei)[pos];
    else        v = ((const int*)ei)[pos];
    return min(max(v, 0), nmax - 1);
}

// ---------------- CSR build --------------------------------------------------
__global__ void k_zero(int n) {
    int i = blockIdx.x * blockDim.x + threadIdx.x;
    if (i < n) { g_deg[i] = 0; g_cursor[i] = 0; }
}
__global__ void k_hist(const void* __restrict__ ei, int E, int Nn) {
    int e = blockIdx.x * blockDim.x + threadIdx.x;
    if (e < E) atomicAdd(&g_deg[load_idx(ei, (size_t)E + e, Nn)], 1);
}
#define SCAN_T 512
__global__ void k_scanA(int n) {
    __shared__ int sh[SCAN_T];
    int b = blockIdx.x, t = threadIdx.x;
    int i = b * SCAN_T + t;
    int v = (i < n) ? g_deg[i] : 0;
    sh[t] = v;
    __syncthreads();
    for (int off = 1; off < SCAN_T; off <<= 1) {
        int u = (t >= off) ? sh[t - off] : 0;
        __syncthreads();
        sh[t] += u;
        __syncthreads();
    }
    if (i < n) g_tmp[i] = sh[t];
    if (t == SCAN_T - 1) g_bsum[b] = sh[t];
}
__global__ void k_scanB(int nb) {
    __shared__ int sh[128];
    int t = threadIdx.x;
    sh[t] = (t < nb) ? g_bsum[t] : 0;
    __syncthreads();
    for (int off = 1; off < 128; off <<= 1) {
        int u = (t >= off) ? sh[t - off] : 0;
        __syncthreads();
        sh[t] += u;
        __syncthreads();
    }
    if (t < nb) g_bsum[t] = sh[t];
}
__global__ void k_scanC(int n) {
    int b = blockIdx.x, t = threadIdx.x;
    int i = b * SCAN_T + t;
    if (i < n) {
        int boff = (b == 0) ? 0 : g_bsum[b - 1];
        g_rowptr[i] = boff + g_tmp[i] - g_deg[i];
        if (i == n - 1) g_rowptr[n] = boff + g_tmp[i];
    }
}
__global__ void k_fill(const void* __restrict__ ei, int E, int Nn) {
    int e = blockIdx.x * blockDim.x + threadIdx.x;
    if (e < E) {
        int s = load_idx(ei, (size_t)e, Nn);
        int d = load_idx(ei, (size_t)E + e, Nn);
        int pos = atomicAdd(&g_cursor[d], 1);
        g_col[g_rowptr[d] + pos] = s;
    }
}

// ---------------- conversions ------------------------------------------------
__global__ void k_cvt(const float* __restrict__ x, bf16* __restrict__ oh,
                      bf16* __restrict__ ol, int n4) {
    int i = blockIdx.x * blockDim.x + threadIdx.x;
    if (i < n4) {
        float4 v = ((const float4*)x)[i];
        bf162 h0, l0, h1, l1;
        split2p(make_float2(v.x, v.y), h0, l0);
        split2p(make_float2(v.z, v.w), h1, l1);
        ((bf162*)oh)[2 * i]     = h0;
        ((bf162*)oh)[2 * i + 1] = h1;
        ((bf162*)ol)[2 * i]     = l0;
        ((bf162*)ol)[2 * i + 1] = l1;
    }
}
// weights -> transposed stacked bf16 hi/lo: Bt[n*512 + k]; k<256: Wrel, else Wroot
__global__ void k_cvtw(const float* __restrict__ Wrel, const float* __restrict__ Wroot,
                       bf16* __restrict__ oh, bf16* __restrict__ ol) {
    int idx = blockIdx.x * blockDim.x + threadIdx.x;   // 0..131071
    int n = idx >> 9, k = idx & 511;
    float w = (k < 256) ? Wrel[k * FD + n] : Wroot[(k - 256) * FD + n];
    bf16 h, l;
    split2(w, h, l);
    oh[idx] = h; ol[idx] = l;
}

// ---------------- aggregation ------------------------------------------------
// variant 1: gather fp32 x (layer 1)
__global__ void k_agg(const float* __restrict__ x, bf16* __restrict__ oh,
                      bf16* __restrict__ ol) {
    int node = blockIdx.x;
    int c = threadIdx.x * 4;
    float4 a0 = make_float4(0.f, 0.f, 0.f, 0.f);
    float4 a1 = make_float4(0.f, 0.f, 0.f, 0.f);
    int beg = g_rowptr[node];
    int end = g_rowptr[node + 1];
    int j = beg;
    for (; j + 1 < end; j += 2) {
        int s0 = g_col[j], s1 = g_col[j + 1];
        float4 v0 = *(const float4*)(x + (size_t)s0 * FD + c);
        float4 v1 = *(const float4*)(x + (size_t)s1 * FD + c);
        a0.x += v0.x; a0.y += v0.y; a0.z += v0.z; a0.w += v0.w;
        a1.x += v1.x; a1.y += v1.y; a1.z += v1.z; a1.w += v1.w;
    }
    if (j < end) {
        int s0 = g_col[j];
        float4 v0 = *(const float4*)(x + (size_t)s0 * FD + c);
        a0.x += v0.x; a0.y += v0.y; a0.z += v0.z; a0.w += v0.w;
    }
    a0.x += a1.x; a0.y += a1.y; a0.z += a1.z; a0.w += a1.w;
    bf162 h0, l0, h1, l1;
    split2p(make_float2(a0.x, a0.y), h0, l0);
    split2p(make_float2(a0.z, a0.w), h1, l1);
    size_t o = (size_t)node * FD + c;
    *(bf162*)(oh + o)     = h0;
    *(bf162*)(oh + o + 2) = h1;
    *(bf162*)(ol + o)     = l0;
    *(bf162*)(ol + o + 2) = l1;
}
// variant 2: gather bf16 hi/lo pair (layers 2-3); hi+lo == h to 2^-17
__global__ void k_agg2(const bf16* __restrict__ xh, const bf16* __restrict__ xl,
                       bf16* __restrict__ oh, bf16* __restrict__ ol) {
    int node = blockIdx.x;
    int c = threadIdx.x * 4;
    float4 a0 = make_float4(0.f, 0.f, 0.f, 0.f);
    int beg = g_rowptr[node];
    int end = g_rowptr[node + 1];
    for (int j = beg; j < end; j++) {
        int s = g_col[j];
        uint2 uh = *(const uint2*)(xh + (size_t)s * FD + c);
        uint2 ul = *(const uint2*)(xl + (size_t)s * FD + c);
        float2 f0 = __bfloat1622float2(*(bf162*)&uh.x);
        float2 f1 = __bfloat1622float2(*(bf162*)&uh.y);
        float2 g0 = __bfloat1622float2(*(bf162*)&ul.x);
        float2 g1 = __bfloat1622float2(*(bf162*)&ul.y);
        a0.x += f0.x + g0.x; a0.y += f0.y + g0.y;
        a0.z += f1.x + g1.x; a0.w += f1.y + g1.y;
    }
    bf162 h0, l0, h1, l1;
    split2p(make_float2(a0.x, a0.y), h0, l0);
    split2p(make_float2(a0.z, a0.w), h1, l1);
    size_t o = (size_t)node * FD + c;
    *(bf162*)(oh + o)     = h0;
    *(bf162*)(oh + o + 2) = h1;
    *(bf162*)(ol + o)     = l0;
    *(bf162*)(ol + o + 2) = l1;
}

// ---------------- HMMA dual-GEMM + bias + ELU (bf16x3, cp.async 2-stage) ------
// CTA: 128 rows x 128 cols (grid.y = col half). K = 512 flattened
// (agg k<256, root k>=256), BK=32/iter, 16 iters. 8 warps 2x4, warp = 64x32.
#define LDT   40                            // padded row stride (80 B, 16B-aligned)
#define TILE_B (128 * LDT * 2)              // 10240 B per tile
#define STAGE_B (4 * TILE_B)                // Ah, Al, Bh, Bl
#define SMEM_DYN (2 * STAGE_B)              // 81920 B

__global__ __launch_bounds__(256)
void k_hmma(const bf16* __restrict__ aggh, const bf16* __restrict__ aggl,
            const bf16* __restrict__ rth,  const bf16* __restrict__ rtl,
            const bf16* __restrict__ Bth,  const bf16* __restrict__ Btl,
            const float* __restrict__ bias,
            float* __restrict__ out32,
            bf16* __restrict__ orth, bf16* __restrict__ ortl, int M) {
    extern __shared__ char dsm[];
    uint32_t sbase = s2u(dsm);

    int t = threadIdx.x, lane = t & 31, wid = t >> 5;
    int wm = wid >> 2, wn = wid & 3;          // 2 x 4 warp grid
    int brow = blockIdx.x * 128;
    int bcol = blockIdx.y * 128;

    float acc[4][4][4];
#pragma unroll
    for (int i = 0; i < 4; i++)
#pragma unroll
        for (int j = 0; j < 4; j++)
#pragma unroll
            for (int r = 0; r < 4; r++) acc[i][j][r] = 0.f;

    // per-thread tile-load coordinates (2 uint4 per tile per thread)
    int r0 = t >> 2, c0 = t & 3;
    int r1 = (t + 256) >> 2, c1 = (t + 256) & 3;
    int ga0 = min(brow + r0, M - 1), ga1 = min(brow + r1, M - 1);
    int gb0 = bcol + r0, gb1 = bcol + r1;
    uint32_t sm0 = (uint32_t)((r0 * LDT + c0 * 8) * 2);
    uint32_t sm1 = (uint32_t)((r1 * LDT + c1 * 8) * 2);

    auto prefetch = [&](int it) {
        int kb = it * 32;
        const bf16 *Ah, *Al;
        int acol;
        if (kb < 256) { Ah = aggh; Al = aggl; acol = kb; }
        else          { Ah = rth;  Al = rtl;  acol = kb - 256; }
        uint32_t sb = sbase + (uint32_t)(it & 1) * STAGE_B;
        cpa16(sb + sm0,              Ah + (size_t)ga0 * FD + acol + c0 * 8);
        cpa16(sb + sm1,              Ah + (size_t)ga1 * FD + acol + c1 * 8);
        cpa16(sb + TILE_B + sm0,     Al + (size_t)ga0 * FD + acol + c0 * 8);
        cpa16(sb + TILE_B + sm1,     Al + (size_t)ga1 * FD + acol + c1 * 8);
        cpa16(sb + 2 * TILE_B + sm0, Bth + (size_t)gb0 * 512 + kb + c0 * 8);
        cpa16(sb + 2 * TILE_B + sm1, Bth + (size_t)gb1 * 512 + kb + c1 * 8);
        cpa16(sb + 3 * TILE_B + sm0, Btl + (size_t)gb0 * 512 + kb + c0 * 8);
        cpa16(sb + 3 * TILE_B + sm1, Btl + (size_t)gb1 * 512 + kb + c1 * 8);
        CP_COMMIT();
    };

    prefetch(0);

    for (int it = 0; it < 16; it++) {
        CP_WAIT0();
        __syncthreads();
        if (it + 1 < 16) prefetch(it + 1);   // other stage; overlaps compute below

        uint32_t sb  = sbase + (uint32_t)(it & 1) * STAGE_B;
        uint32_t uAh = sb, uAl = sb + TILE_B;
        uint32_t uBh = sb + 2 * TILE_B, uBl = sb + 3 * TILE_B;

#pragma unroll
        for (int ks = 0; ks < 2; ks++) {
            uint32_t aoff = (uint32_t)(((wm * 64 + (lane & 15)) * LDT
                                        + ks * 16 + (lane >> 4) * 8) * 2);
            uint32_t boff = (uint32_t)(((wn * 32 + (lane & 15)) * LDT
                                        + ks * 16 + (lane >> 4) * 8) * 2);
            uint32_t ah[4][4], al[4][4];
#pragma unroll
            for (int mf = 0; mf < 4; mf++) {
                ldm4(ah[mf], uAh + aoff + mf * 16 * LDT * 2);
                ldm4(al[mf], uAl + aoff + mf * 16 * LDT * 2);
            }
            uint32_t bh[4][2], bl[4][2];
#pragma unroll
            for (int np = 0; np < 2; np++) {
                uint32_t rh[4], rl[4];
                ldm4(rh, uBh + boff + np * 16 * LDT * 2);
                ldm4(rl, uBl + boff + np * 16 * LDT * 2);
                bh[2 * np][0] = rh[0]; bh[2 * np + 1][0] = rh[1];
                bh[2 * np][1] = rh[2]; bh[2 * np + 1][1] = rh[3];
                bl[2 * np][0] = rl[0]; bl[2 * np + 1][0] = rl[1];
                bl[2 * np][1] = rl[2]; bl[2 * np + 1][1] = rl[3];
            }
#pragma unroll
            for (int mf = 0; mf < 4; mf++)
#pragma unroll
                for (int nf = 0; nf < 4; nf++) {
                    mma16816(acc[mf][nf], ah[mf], bh[nf]);   // Ah*Bh
                    mma16816(acc[mf][nf], ah[mf], bl[nf]);   // Ah*Bl
                    mma16816(acc[mf][nf], al[mf], bh[nf]);   // Al*Bh
                }
        }
    }

    // epilogue: bias (reg-cached) + fast ELU + stores
    float2 bias2[4];
#pragma unroll
    for (int nf = 0; nf < 4; nf++) {
        int gcol = bcol + wn * 32 + nf * 8 + (lane & 3) * 2;
        bias2[nf] = *(const float2*)(bias + gcol);
    }
#pragma unroll
    for (int mf = 0; mf < 4; mf++) {
#pragma unroll
        for (int half = 0; half < 2; half++) {
            int grow = brow + wm * 64 + mf * 16 + (lane >> 2) + half * 8;
            if (grow < M) {
#pragma unroll
                for (int nf = 0; nf < 4; nf++) {
                    int gcol = bcol + wn * 32 + nf * 8 + (lane & 3) * 2;
                    float v0 = elu1(acc[mf][nf][half * 2]     + bias2[nf].x);
                    float v1 = elu1(acc[mf][nf][half * 2 + 1] + bias2[nf].y);
                    size_t go = (size_t)grow * FD + gcol;
                    if (out32) {
                        *(float2*)(out32 + go) = make_float2(v0, v1);
                    }
                    if (orth) {
                        bf162 hp, lp;
                        split2p(make_float2(v0, v1), hp, lp);
                        *(bf162*)(orth + go) = hp;
                        *(bf162*)(ortl + go) = lp;
                    }
                }
            }
        }
    }
}

// ---------------- launch -----------------------------------------------------
extern "C" void kernel_launch(void* const* d_in, const int* in_sizes, int n_in,
                              void* d_out, int out_size) {
    const float* x   = (const float*)d_in[0];
    const void*  ei  = d_in[1];
    const float* W1r = (const float*)d_in[2];
    const float* b1  = (const float*)d_in[3];
    const float* W1o = (const float*)d_in[4];
    const float* W2r = (const float*)d_in[5];
    const float* b2  = (const float*)d_in[6];
    const float* W2o = (const float*)d_in[7];
    const float* W3r = (const float*)d_in[8];
    const float* b3  = (const float*)d_in[9];
    const float* W3o = (const float*)d_in[10];
    float* out = (float*)d_out;

    int Nn = in_sizes[0] / FD;      // 50000
    int E  = in_sizes[1] / 2;       // 800000

    bf16 *aggh, *aggl, *rt0h, *rt0l, *rt1h, *rt1l, *Bth, *Btl;
    cudaGetSymbolAddress((void**)&aggh, g_aggh);
    cudaGetSymbolAddress((void**)&aggl, g_aggl);
    cudaGetSymbolAddress((void**)&rt0h, g_rt0h);
    cudaGetSymbolAddress((void**)&rt0l, g_rt0l);
    cudaGetSymbolAddress((void**)&rt1h, g_rt1h);
    cudaGetSymbolAddress((void**)&rt1l, g_rt1l);
    cudaGetSymbolAddress((void**)&Bth,  g_Bth);
    cudaGetSymbolAddress((void**)&Btl,  g_Btl);

    cudaFuncSetAttribute(k_hmma, cudaFuncAttributeMaxDynamicSharedMemorySize, SMEM_DYN);

    // CSR build
    k_detect<<<1, 1>>>((const int*)ei);
    k_zero<<<(Nn + 255) / 256, 256>>>(Nn);
    k_hist<<<(E + 255) / 256, 256>>>(ei, E, Nn);
    int nsb = (Nn + SCAN_T - 1) / SCAN_T;
    k_scanA<<<nsb, SCAN_T>>>(Nn);
    k_scanB<<<1, 128>>>(nsb);
    k_scanC<<<nsb, SCAN_T>>>(Nn);
    k_fill<<<(E + 255) / 256, 256>>>(ei, E, Nn);

    // weight + input conversions
    k_cvtw<<<512, 256>>>(W1r, W1o, Bth,                 Btl);
    k_cvtw<<<512, 256>>>(W2r, W2o, Bth + 512 * 256,     Btl + 512 * 256);
    k_cvtw<<<512, 256>>>(W3r, W3o, Bth + 2 * 512 * 256, Btl + 2 * 512 * 256);
    int n4 = Nn * FD / 4;
    k_cvt<<<(n4 + 255) / 256, 256>>>(x, rt0h, rt0l, n4);

    dim3 gg((Nn + 127) / 128, 2);

    // layer 1: h0 kept only as bf16 hi/lo (rt1)
    k_agg<<<Nn, 64>>>(x, aggh, aggl);
    k_hmma<<<gg, 256, SMEM_DYN>>>(aggh, aggl, rt0h, rt0l, Bth, Btl,
                                  b1, (float*)nullptr, rt1h, rt1l, Nn);
    // layer 2: h1 -> rt0 (x split no longer needed)
    k_agg2<<<Nn, 64>>>(rt1h, rt1l, aggh, aggl);
    k_hmma<<<gg, 256, SMEM_DYN>>>(aggh, aggl, rt1h, rt1l,
                                  Bth + 512 * 256, Btl + 512 * 256,
                                  b2, (float*)nullptr, rt0h, rt0l, Nn);
    // layer 3: final fp32 output only
    k_agg2<<<Nn, 64>>>(rt0h, rt0l, aggh, aggl);
    k_hmma<<<gg, 256, SMEM_DYN>>>(aggh, aggl, rt0h, rt0l,
                                  Bth + 2 * 512 * 256, Btl + 2 * 512 * 256,
                                  b3, out, (bf16*)nullptr, (bf16*)nullptr, Nn);
}